// round 15
// baseline (speedup 1.0000x reference)
#include <cuda_runtime.h>
#include <cuda_fp16.h>
#include <cstdint>

#define NMAX    50000
#define IN_DIM  256
#define W_DIM   128
#define BM      128
#define BN      128
#define KC      64
#define NCH     (IN_DIM / KC)
#define AP      72

// edge bucketing
#define EMAX    1600000
#define BSH     8
#define BNODES  256
#define NB      ((NMAX + BNODES - 1) / BNODES)   // 196
#define SPLIT   4
#define SC_PER  3328                              // edges per scatter CTA

// Quantized QK, int16 split into bytes. Per node row (512B):
//   [0,128) q hi (s8)  [128,256) q lo (u8)  [256,384) k hi (s8)  [384,512) k lo (u8)
__device__ char d_QK8[(size_t)NMAX * 512];
__device__ float d_S[2 * NMAX];            // q scales then k scales
__device__ half d_Wh[256 * IN_DIM];
__device__ half d_Xh[(size_t)NMAX * IN_DIM];
// sorted edges
__device__ unsigned d_EP[EMAX];            // s | d<<16
__device__ int      d_EI[EMAX];            // original edge index
__device__ int d_cnt[NB];
__device__ int d_boff[NB + 1];
__device__ int d_bcur[NB];

#define TILE_H   (BM * AP)
#define BUF_H    (2 * TILE_H)
#define GEMM_SMEM (2 * BUF_H * 2)                 // 73728 B
#define EDGE_SMEM (BNODES * 256)                  // 65536 B

#define MMA16816(c, a, b)                                                     \
    asm volatile(                                                             \
        "mma.sync.aligned.m16n8k16.row.col.f32.f16.f16.f32 "                  \
        "{%0,%1,%2,%3}, {%4,%5,%6,%7}, {%8,%9}, {%0,%1,%2,%3};"               \
        : "+f"((c)[0]), "+f"((c)[1]), "+f"((c)[2]), "+f"((c)[3])              \
        : "r"((a)[0]), "r"((a)[1]), "r"((a)[2]), "r"((a)[3]),                 \
          "r"((b)[0]), "r"((b)[1]))

#define CP_ASYNC16(smem_u32_, gptr)                                           \
    asm volatile("cp.async.ca.shared.global [%0], [%1], 16;"                  \
                 :: "r"(smem_u32_), "l"(gptr) : "memory")
#define CP_COMMIT()  asm volatile("cp.async.commit_group;" ::: "memory")
#define CP_WAIT(n)   asm volatile("cp.async.wait_group %0;" :: "n"(n) : "memory")

__device__ __forceinline__ uint32_t smem_u32(const void* p) {
    uint32_t a;
    asm("{ .reg .u64 t; cvta.to.shared.u64 t, %1; cvt.u32.u64 %0, t; }" : "=r"(a) : "l"(p));
    return a;
}
__device__ __forceinline__ int dp4a_ss(int a, int b, int c) {
    int d; asm("dp4a.s32.s32 %0,%1,%2,%3;" : "=r"(d) : "r"(a), "r"(b), "r"(c)); return d;
}
__device__ __forceinline__ int dp4a_su(int a, int b, int c) {
    int d; asm("dp4a.s32.u32 %0,%1,%2,%3;" : "=r"(d) : "r"(a), "r"(b), "r"(c)); return d;
}
__device__ __forceinline__ int dp4a_us(int a, int b, int c) {
    int d; asm("dp4a.u32.s32 %0,%1,%2,%3;" : "=r"(d) : "r"(a), "r"(b), "r"(c)); return d;
}
__device__ __forceinline__ int dp4a_uu(int a, int b, int c) {
    int d; asm("dp4a.u32.u32 %0,%1,%2,%3;" : "=r"(d) : "r"(a), "r"(b), "r"(c)); return d;
}

// ---------------------------------------------------------------------------
// One-time fp16 pack of W and X.
// ---------------------------------------------------------------------------
#define W_F4 (256 * IN_DIM / 4)
__global__ __launch_bounds__(256) void prep_all(
    const float* __restrict__ Wq, const float* __restrict__ Wk,
    const float* __restrict__ X, int x_f4)
{
    const int i = blockIdx.x * 256 + threadIdx.x;
    if (i < W_F4) {
        const int base = i * 4;
        const int n = base >> 8, col = base & 255;
        const float4 v = (n < W_DIM)
            ? *(const float4*)(Wq + n * IN_DIM + col)
            : *(const float4*)(Wk + (n - W_DIM) * IN_DIM + col);
        *(half2*)(d_Wh + base)     = __floats2half2_rn(v.x, v.y);
        *(half2*)(d_Wh + base + 2) = __floats2half2_rn(v.z, v.w);
    } else {
        const int j = i - W_F4;
        if (j < x_f4) {
            const int base = j * 4;
            const float4 v = *(const float4*)(X + base);
            *(half2*)(d_Xh + base)     = __floats2half2_rn(v.x, v.y);
            *(half2*)(d_Xh + base + 2) = __floats2half2_rn(v.z, v.w);
        }
    }
}

// ---------------------------------------------------------------------------
// Edge bucketing: zero -> histogram -> scan -> two-phase scatter.
// ---------------------------------------------------------------------------
__global__ void zero_cnt() {
    if (threadIdx.x < NB) d_cnt[threadIdx.x] = 0;
}

__global__ __launch_bounds__(256) void hist_k(const int* __restrict__ ei, int E, int M) {
    __shared__ int sh[NB];
    for (int i = threadIdx.x; i < NB; i += 256) sh[i] = 0;
    __syncthreads();
    const int base = blockIdx.x * SC_PER;
    for (int off = threadIdx.x; off < SC_PER; off += 256) {
        const int idx = base + off;
        if (idx < E) {
            const int s = min(max(ei[idx], 0), M - 1);
            atomicAdd(&sh[s >> BSH], 1);
        }
    }
    __syncthreads();
    for (int i = threadIdx.x; i < NB; i += 256)
        if (sh[i]) atomicAdd(&d_cnt[i], sh[i]);
}

__global__ void scan_k() {
    if (threadIdx.x == 0) {
        int acc = 0;
        for (int i = 0; i < NB; ++i) {
            d_boff[i] = acc; d_bcur[i] = acc; acc += d_cnt[i];
        }
        d_boff[NB] = acc;
    }
}

__global__ __launch_bounds__(256) void scatter_k(const int* __restrict__ ei, int E, int M) {
    __shared__ int sh_cnt[NB];
    __shared__ int sh_base[NB];
    __shared__ unsigned short sh_rank[SC_PER];
    __shared__ unsigned char  sh_bb[SC_PER];
    for (int i = threadIdx.x; i < NB; i += 256) sh_cnt[i] = 0;
    __syncthreads();
    const int base = blockIdx.x * SC_PER;
    // phase A: local ranks
    for (int off = threadIdx.x; off < SC_PER; off += 256) {
        const int idx = base + off;
        if (idx < E) {
            const int s = min(max(ei[idx], 0), M - 1);
            const int b = s >> BSH;
            sh_rank[off] = (unsigned short)atomicAdd(&sh_cnt[b], 1);
            sh_bb[off]   = (unsigned char)b;
        }
    }
    __syncthreads();
    // phase B0: reserve global slots
    for (int i = threadIdx.x; i < NB; i += 256)
        if (sh_cnt[i]) sh_base[i] = atomicAdd(&d_bcur[i], sh_cnt[i]);
    __syncthreads();
    // phase B: write packed edges
    for (int off = threadIdx.x; off < SC_PER; off += 256) {
        const int idx = base + off;
        if (idx < E) {
            const int s = min(max(ei[idx], 0), M - 1);
            const int d = min(max(ei[E + idx], 0), M - 1);
            const int pos = sh_base[sh_bb[off]] + (int)sh_rank[off];
            d_EP[pos] = (unsigned)s | ((unsigned)d << 16);
            d_EI[pos] = idx;
        }
    }
}

// ---------------------------------------------------------------------------
// GEMM (unchanged from R14): fp16 MMA, cp.async double buffer, 2 CTAs/SM,
// fused int16 quantize -> s8hi/u8lo.
// ---------------------------------------------------------------------------
__global__ void __launch_bounds__(256, 2) gemm_qk_mma(
    const float* __restrict__ Bq, const float* __restrict__ Bk, int M)
{
    extern __shared__ half sm[];
    const float* __restrict__ Bv = blockIdx.y ? Bk : Bq;

    const int tid  = threadIdx.x;
    const int wid  = tid >> 5;
    const int lane = tid & 31;
    const int g    = lane >> 2;
    const int t    = lane & 3;
    const int wm   = (wid & 3) * 32;
    const int wn   = (wid >> 2) * 64;
    const int row0 = blockIdx.x * BM;
    const int nbase = blockIdx.y * BN;

    const int s_row = tid >> 3;
    const int s_seg = (tid & 7) * 16;

    float c[2][8][4];
    #pragma unroll
    for (int mt = 0; mt < 2; ++mt)
        #pragma unroll
        for (int nt = 0; nt < 8; ++nt)
            #pragma unroll
            for (int i = 0; i < 4; ++i) c[mt][nt][i] = 0.f;

    auto issue_chunk = [&](int ch, int bsel) {
        half* As = sm + bsel * BUF_H;
        half* Bs = As + TILE_H;
        const uint32_t as_u32 = smem_u32(As);
        const uint32_t bs_u32 = smem_u32(Bs);
        #pragma unroll
        for (int i = 0; i < 4; ++i) {
            const int row = s_row + i * 32;
            const int ar  = min(row0 + row, M - 1);
            const char* asrc = (const char*)(d_Xh + (size_t)ar * IN_DIM + ch * KC) + s_seg;
            CP_ASYNC16(as_u32 + row * (AP * 2) + s_seg, asrc);
            const char* bsrc = (const char*)(d_Wh + (size_t)(nbase + row) * IN_DIM + ch * KC) + s_seg;
            CP_ASYNC16(bs_u32 + row * (AP * 2) + s_seg, bsrc);
        }
        CP_COMMIT();
    };

    issue_chunk(0, 0);

    for (int ch = 0; ch < NCH; ++ch) {
        if (ch + 1 < NCH) { issue_chunk(ch + 1, (ch + 1) & 1); CP_WAIT(1); }
        else             { CP_WAIT(0); }
        __syncthreads();

        {
            half* As = sm + (ch & 1) * BUF_H;
            half* Bs = As + TILE_H;
            #pragma unroll
            for (int ks = 0; ks < KC / 16; ++ks) {
                const int kb = ks * 16 + 2 * t;
                uint32_t ah[2][4];
                #pragma unroll
                for (int mt = 0; mt < 2; ++mt) {
                    const int rb = wm + mt * 16 + g;
                    ah[mt][0] = *(const uint32_t*)(As + (rb    ) * AP + kb);
                    ah[mt][1] = *(const uint32_t*)(As + (rb + 8) * AP + kb);
                    ah[mt][2] = *(const uint32_t*)(As + (rb    ) * AP + kb + 8);
                    ah[mt][3] = *(const uint32_t*)(As + (rb + 8) * AP + kb + 8);
                }
                #pragma unroll
                for (int nt = 0; nt < 8; ++nt) {
                    const int nb = wn + nt * 8 + g;
                    uint32_t bh[2];
                    bh[0] = *(const uint32_t*)(Bs + nb * AP + kb);
                    bh[1] = *(const uint32_t*)(Bs + nb * AP + kb + 8);
                    #pragma unroll
                    for (int mt = 0; mt < 2; ++mt)
                        MMA16816(c[mt][nt], ah[mt], bh);
                }
            }
        }
        __syncthreads();
    }

    float rmax[2][2];
    #pragma unroll
    for (int mt = 0; mt < 2; ++mt) { rmax[mt][0] = 0.f; rmax[mt][1] = 0.f; }
    #pragma unroll
    for (int mt = 0; mt < 2; ++mt)
        #pragma unroll
        for (int nt = 0; nt < 8; ++nt) {
            const float2 b = *(const float2*)(Bv + wn + nt * 8 + 2 * t);
            c[mt][nt][0] += b.x; c[mt][nt][1] += b.y;
            c[mt][nt][2] += b.x; c[mt][nt][3] += b.y;
            rmax[mt][0] = fmaxf(rmax[mt][0],
                                fmaxf(fabsf(c[mt][nt][0]), fabsf(c[mt][nt][1])));
            rmax[mt][1] = fmaxf(rmax[mt][1],
                                fmaxf(fabsf(c[mt][nt][2]), fabsf(c[mt][nt][3])));
        }
    #pragma unroll
    for (int mt = 0; mt < 2; ++mt)
        #pragma unroll
        for (int hh = 0; hh < 2; ++hh) {
            float v = rmax[mt][hh];
            v = fmaxf(v, __shfl_xor_sync(0xffffffffu, v, 1));
            v = fmaxf(v, __shfl_xor_sync(0xffffffffu, v, 2));
            rmax[mt][hh] = v;
        }
    float* smax = (float*)sm;
    float* sinv = (float*)sm + 256;
    if (t == 0) {
        const int wh = wid >> 2;
        #pragma unroll
        for (int mt = 0; mt < 2; ++mt) {
            smax[wh * 128 + wm + mt * 16 + g]     = rmax[mt][0];
            smax[wh * 128 + wm + mt * 16 + g + 8] = rmax[mt][1];
        }
    }
    __syncthreads();
    if (tid < 128) {
        const float m = fmaxf(smax[tid], smax[128 + tid]);
        sinv[tid] = (m > 0.f) ? (32767.0f / m) : 0.f;
        const int r = row0 + tid;
        if (r < M)
            d_S[blockIdx.y * NMAX + r] = m * (1.0f / 32767.0f);
    }
    __syncthreads();

    const int half_off = blockIdx.y * 256;
    #pragma unroll
    for (int mt = 0; mt < 2; ++mt) {
        const int rr0 = wm + mt * 16 + g;
        const int rr1 = rr0 + 8;
        const float i0 = sinv[rr0];
        const float i1 = sinv[rr1];
        const int r_lo = row0 + rr0, r_hi = row0 + rr1;
        #pragma unroll
        for (int nt = 0; nt < 8; ++nt) {
            const int colh = wn + nt * 8 + 2 * t;
            if (r_lo < M) {
                int v0 = __float2int_rn(c[mt][nt][0] * i0);
                int v1 = __float2int_rn(c[mt][nt][1] * i0);
                v0 = max(min(v0, 32767), -32767);
                v1 = max(min(v1, 32767), -32767);
                char* bp = d_QK8 + (size_t)r_lo * 512 + half_off;
                *(char2*)(bp + colh) = make_char2((char)(v0 >> 8), (char)(v1 >> 8));
                *(uchar2*)(bp + 128 + colh) =
                    make_uchar2((unsigned char)(v0 & 255), (unsigned char)(v1 & 255));
            }
            if (r_hi < M) {
                int v0 = __float2int_rn(c[mt][nt][2] * i1);
                int v1 = __float2int_rn(c[mt][nt][3] * i1);
                v0 = max(min(v0, 32767), -32767);
                v1 = max(min(v1, 32767), -32767);
                char* bp = d_QK8 + (size_t)r_hi * 512 + half_off;
                *(char2*)(bp + colh) = make_char2((char)(v0 >> 8), (char)(v1 >> 8));
                *(uchar2*)(bp + 128 + colh) =
                    make_uchar2((unsigned char)(v0 & 255), (unsigned char)(v1 & 255));
            }
        }
    }
}

// ---------------------------------------------------------------------------
// Sorted edge kernel: CTA = (bucket, part). Stage the bucket's 256 q-rows
// (64KB) in smem; stream edges reading q from smem, k from L2 via dp4a.
// ---------------------------------------------------------------------------
__global__ void __launch_bounds__(256) edge_attn_sorted(
    float* __restrict__ out, int M)
{
    extern __shared__ char sq[];   // 64KB: q halves of this bucket's rows
    const int b = blockIdx.x / SPLIT;
    const int p = blockIdx.x % SPLIT;
    const int nbase = b * BNODES;
    const int nrows = min(BNODES, M - nbase);

    for (int i = threadIdx.x; i < nrows * 16; i += 256) {
        const int r = i >> 4, seg = i & 15;
        *(int4*)(sq + r * 256 + seg * 16) =
            *(const int4*)(d_QK8 + (size_t)(nbase + r) * 512 + seg * 16);
    }
    __syncthreads();

    const int start = d_boff[b];
    const int cnt   = d_boff[b + 1] - start;
    const int per   = (cnt + SPLIT - 1) / SPLIT;
    const int lo    = start + p * per;
    const int hi    = min(start + cnt, lo + per);

    const int group = threadIdx.x >> 3;
    const int sub   = threadIdx.x & 7;

    for (int i = lo + group; i < hi; i += 32) {
        const unsigned pk = d_EP[i];
        const int s = (int)(pk & 0xFFFFu);
        const int d = (int)(pk >> 16);

        const char* qb = sq + (s - nbase) * 256;
        const char* kb = d_QK8 + (size_t)d * 512 + 256;

        const int4 qh = *(const int4*)(qb + sub * 16);
        const int4 ql = *(const int4*)(qb + 128 + sub * 16);
        const int4 kh = *(const int4*)(kb + sub * 16);
        const int4 kl = *(const int4*)(kb + 128 + sub * 16);

        int hh = 0, hl = 0, lh = 0, ll = 0;
        const int* qhp = (const int*)&qh; const int* qlp = (const int*)&ql;
        const int* khp = (const int*)&kh; const int* klp = (const int*)&kl;
        #pragma unroll
        for (int j = 0; j < 4; ++j) {
            hh = dp4a_ss(qhp[j], khp[j], hh);
            hl = dp4a_su(qhp[j], klp[j], hl);
            lh = dp4a_us(qlp[j], khp[j], lh);
            ll = dp4a_uu(qlp[j], klp[j], ll);
        }
        float acc = 65536.0f * (float)hh + 256.0f * (float)(hl + lh) + (float)ll;

        acc += __shfl_xor_sync(0xffffffffu, acc, 1);
        acc += __shfl_xor_sync(0xffffffffu, acc, 2);
        acc += __shfl_xor_sync(0xffffffffu, acc, 4);

        if (sub == 0) {
            const float scale = d_S[s] * d_S[NMAX + d] * 0.08838834764831845f;
            out[d_EI[i]] = acc * scale;
        }
    }
}

// ---------------------------------------------------------------------------
extern "C" void kernel_launch(void* const* d_in, const int* in_sizes, int n_in,
                              void* d_out, int out_size)
{
    const float *X = nullptr, *Wq = nullptr, *Bq = nullptr, *Wk = nullptr, *Bk = nullptr;
    const int   *ei = nullptr;
    int ei_elems = 0, x_elems = 0;

    for (int i = 0; i < n_in; ++i) {
        const int sz = in_sizes[i];
        if (sz == W_DIM * IN_DIM) {
            if (!Wq) Wq = (const float*)d_in[i];
            else     Wk = (const float*)d_in[i];
        } else if (sz == W_DIM) {
            if (!Bq) Bq = (const float*)d_in[i];
            else     Bk = (const float*)d_in[i];
        } else if (sz > 4000000) {
            X = (const float*)d_in[i];
            x_elems = sz;
        } else {
            ei = (const int*)d_in[i];
            ei_elems = sz;
        }
    }

    const int M = x_elems / IN_DIM;    // 50000
    const int E = ei_elems / 2;        // 1600000
    const int x_f4 = x_elems / 4;
    float* out = (float*)d_out;

    static int attr_set = 0;
    if (!attr_set) {
        cudaFuncSetAttribute(gemm_qk_mma,
                             cudaFuncAttributeMaxDynamicSharedMemorySize, GEMM_SMEM);
        cudaFuncSetAttribute(edge_attn_sorted,
                             cudaFuncAttributeMaxDynamicSharedMemorySize, EDGE_SMEM);
        attr_set = 1;
    }

    const int prep_total = W_F4 + x_f4;
    prep_all<<<(prep_total + 255) / 256, 256>>>(Wq, Wk, X, x_f4);

    // edge bucketing (independent of GEMM; serialized on stream)
    const int sc_blocks = (E + SC_PER - 1) / SC_PER;
    zero_cnt<<<1, 256>>>();
    hist_k<<<sc_blocks, 256>>>(ei, E, M);
    scan_k<<<1, 32>>>();
    scatter_k<<<sc_blocks, 256>>>(ei, E, M);

    dim3 grid_g((M + BM - 1) / BM, 2);
    gemm_qk_mma<<<grid_g, 256, GEMM_SMEM>>>(Bq, Bk, M);

    edge_attn_sorted<<<NB * SPLIT, 256, EDGE_SMEM>>>(out, M);
}

// round 16
// speedup vs baseline: 1.9189x; 1.9189x over previous
#include <cuda_runtime.h>
#include <cuda_fp16.h>
#include <cstdint>

#define NMAX    50000
#define IN_DIM  256
#define W_DIM   128
#define BM      128           // M rows per CTA
#define BN      128           // N cols per CTA (blockIdx.y -> Wq/Wk)
#define KC      64            // K chunk
#define NCH     (IN_DIM / KC) // 4 chunks
#define AP      72            // padded row stride (halves): conflict-free LDS

// Quantized QK, int16 split into bytes. Per node row (512B):
//   [0,128) q hi (s8)  [128,256) q lo (u8)  [256,384) k hi (s8)  [384,512) k lo (u8)
__device__ char d_QK8[(size_t)NMAX * 512];
// Per-row-half scales: [0,NMAX) = q, [NMAX,2*NMAX) = k. value = int * scale.
__device__ float d_S[2 * NMAX];
// fp16 weights: rows 0-127 = Wq, 128-255 = Wk
__device__ half d_Wh[256 * IN_DIM];
// fp16 inputs
__device__ half d_Xh[(size_t)NMAX * IN_DIM];

// smem: [buf][2 tiles][BM*AP halves]; tiles: 0=A 1=B
#define TILE_H   (BM * AP)                    // 9216 halves
#define BUF_H    (2 * TILE_H)                 // 18432 halves
#define SMEM_TOTAL (2 * BUF_H * 2)            // 73728 B

// m16n8k16 f16 MMA, fp32 accumulate
#define MMA16816(c, a, b)                                                     \
    asm volatile(                                                             \
        "mma.sync.aligned.m16n8k16.row.col.f32.f16.f16.f32 "                  \
        "{%0,%1,%2,%3}, {%4,%5,%6,%7}, {%8,%9}, {%0,%1,%2,%3};"               \
        : "+f"((c)[0]), "+f"((c)[1]), "+f"((c)[2]), "+f"((c)[3])              \
        : "r"((a)[0]), "r"((a)[1]), "r"((a)[2]), "r"((a)[3]),                 \
          "r"((b)[0]), "r"((b)[1]))

// cp.async 16B gmem->smem
#define CP_ASYNC16(smem_u32_, gptr)                                           \
    asm volatile("cp.async.ca.shared.global [%0], [%1], 16;"                  \
                 :: "r"(smem_u32_), "l"(gptr) : "memory")
#define CP_COMMIT()  asm volatile("cp.async.commit_group;" ::: "memory")
#define CP_WAIT(n)   asm volatile("cp.async.wait_group %0;" :: "n"(n) : "memory")

__device__ __forceinline__ uint32_t smem_u32(const void* p) {
    uint32_t a;
    asm("{ .reg .u64 t; cvta.to.shared.u64 t, %1; cvt.u32.u64 %0, t; }" : "=r"(a) : "l"(p));
    return a;
}

// dp4a variants
__device__ __forceinline__ int dp4a_ss(int a, int b, int c) {
    int d; asm("dp4a.s32.s32 %0,%1,%2,%3;" : "=r"(d) : "r"(a), "r"(b), "r"(c)); return d;
}
__device__ __forceinline__ int dp4a_su(int a, int b, int c) {
    int d; asm("dp4a.s32.u32 %0,%1,%2,%3;" : "=r"(d) : "r"(a), "r"(b), "r"(c)); return d;
}
__device__ __forceinline__ int dp4a_us(int a, int b, int c) {
    int d; asm("dp4a.u32.s32 %0,%1,%2,%3;" : "=r"(d) : "r"(a), "r"(b), "r"(c)); return d;
}
__device__ __forceinline__ int dp4a_uu(int a, int b, int c) {
    int d; asm("dp4a.u32.u32 %0,%1,%2,%3;" : "=r"(d) : "r"(a), "r"(b), "r"(c)); return d;
}

// ---------------------------------------------------------------------------
// One-time fp16 pack of W ([Wq;Wk] -> d_Wh) and X (-> d_Xh).
// ---------------------------------------------------------------------------
#define W_F4 (256 * IN_DIM / 4)   // 16384
__global__ __launch_bounds__(256) void prep_all(
    const float* __restrict__ Wq, const float* __restrict__ Wk,
    const float* __restrict__ X, int x_f4)
{
    const int i = blockIdx.x * 256 + threadIdx.x;
    if (i < W_F4) {
        const int base = i * 4;
        const int n = base >> 8, col = base & 255;
        const float4 v = (n < W_DIM)
            ? *(const float4*)(Wq + n * IN_DIM + col)
            : *(const float4*)(Wk + (n - W_DIM) * IN_DIM + col);
        *(half2*)(d_Wh + base)     = __floats2half2_rn(v.x, v.y);
        *(half2*)(d_Wh + base + 2) = __floats2half2_rn(v.z, v.w);
    } else {
        const int j = i - W_F4;
        if (j < x_f4) {
            const int base = j * 4;
            const float4 v = *(const float4*)(X + base);
            *(half2*)(d_Xh + base)     = __floats2half2_rn(v.x, v.y);
            *(half2*)(d_Xh + base + 2) = __floats2half2_rn(v.z, v.w);
        }
    }
}

// ---------------------------------------------------------------------------
// Tensor-core projection + fused int16 quantization (stored as s8hi/u8lo).
// Pure fp16 GEMM on pre-converted fp16 A/B; cp.async double-buffer staging;
// 2 CTAs/SM. RMS err ~4e-4 (budget 1e-3).
// ---------------------------------------------------------------------------
__global__ void __launch_bounds__(256, 2) gemm_qk_mma(
    const float* __restrict__ Bq, const float* __restrict__ Bk, int M)
{
    extern __shared__ half sm[];
    const float* __restrict__ Bv = blockIdx.y ? Bk : Bq;

    const int tid  = threadIdx.x;
    const int wid  = tid >> 5;
    const int lane = tid & 31;
    const int g    = lane >> 2;
    const int t    = lane & 3;
    const int wm   = (wid & 3) * 32;
    const int wn   = (wid >> 2) * 64;
    const int row0 = blockIdx.x * BM;
    const int nbase = blockIdx.y * BN;

    const int s_row = tid >> 3;
    const int s_seg = (tid & 7) * 16;

    float c[2][8][4];
    #pragma unroll
    for (int mt = 0; mt < 2; ++mt)
        #pragma unroll
        for (int nt = 0; nt < 8; ++nt)
            #pragma unroll
            for (int i = 0; i < 4; ++i) c[mt][nt][i] = 0.f;

    auto issue_chunk = [&](int ch, int bsel) {
        half* As = sm + bsel * BUF_H;
        half* Bs = As + TILE_H;
        const uint32_t as_u32 = smem_u32(As);
        const uint32_t bs_u32 = smem_u32(Bs);
        #pragma unroll
        for (int i = 0; i < 4; ++i) {
            const int row = s_row + i * 32;
            const int ar  = min(row0 + row, M - 1);
            const char* asrc = (const char*)(d_Xh + (size_t)ar * IN_DIM + ch * KC) + s_seg;
            CP_ASYNC16(as_u32 + row * (AP * 2) + s_seg, asrc);
            const char* bsrc = (const char*)(d_Wh + (size_t)(nbase + row) * IN_DIM + ch * KC) + s_seg;
            CP_ASYNC16(bs_u32 + row * (AP * 2) + s_seg, bsrc);
        }
        CP_COMMIT();
    };

    issue_chunk(0, 0);

    for (int ch = 0; ch < NCH; ++ch) {
        if (ch + 1 < NCH) { issue_chunk(ch + 1, (ch + 1) & 1); CP_WAIT(1); }
        else             { CP_WAIT(0); }
        __syncthreads();

        {
            half* As = sm + (ch & 1) * BUF_H;
            half* Bs = As + TILE_H;

            #pragma unroll
            for (int ks = 0; ks < KC / 16; ++ks) {
                const int kb = ks * 16 + 2 * t;

                uint32_t ah[2][4];
                #pragma unroll
                for (int mt = 0; mt < 2; ++mt) {
                    const int rb = wm + mt * 16 + g;
                    ah[mt][0] = *(const uint32_t*)(As + (rb    ) * AP + kb);
                    ah[mt][1] = *(const uint32_t*)(As + (rb + 8) * AP + kb);
                    ah[mt][2] = *(const uint32_t*)(As + (rb    ) * AP + kb + 8);
                    ah[mt][3] = *(const uint32_t*)(As + (rb + 8) * AP + kb + 8);
                }
                #pragma unroll
                for (int nt = 0; nt < 8; ++nt) {
                    const int nb = wn + nt * 8 + g;
                    uint32_t bh[2];
                    bh[0] = *(const uint32_t*)(Bs + nb * AP + kb);
                    bh[1] = *(const uint32_t*)(Bs + nb * AP + kb + 8);
                    #pragma unroll
                    for (int mt = 0; mt < 2; ++mt)
                        MMA16816(c[mt][nt], ah[mt], bh);
                }
            }
        }
        __syncthreads();
    }

    // ====== epilogue: bias + row absmax + int16 quantize -> s8hi/u8lo ======
    float rmax[2][2];
    #pragma unroll
    for (int mt = 0; mt < 2; ++mt) { rmax[mt][0] = 0.f; rmax[mt][1] = 0.f; }
    #pragma unroll
    for (int mt = 0; mt < 2; ++mt)
        #pragma unroll
        for (int nt = 0; nt < 8; ++nt) {
            const float2 b = *(const float2*)(Bv + wn + nt * 8 + 2 * t);
            c[mt][nt][0] += b.x; c[mt][nt][1] += b.y;
            c[mt][nt][2] += b.x; c[mt][nt][3] += b.y;
            rmax[mt][0] = fmaxf(rmax[mt][0],
                                fmaxf(fabsf(c[mt][nt][0]), fabsf(c[mt][nt][1])));
            rmax[mt][1] = fmaxf(rmax[mt][1],
                                fmaxf(fabsf(c[mt][nt][2]), fabsf(c[mt][nt][3])));
        }
    #pragma unroll
    for (int mt = 0; mt < 2; ++mt)
        #pragma unroll
        for (int hh = 0; hh < 2; ++hh) {
            float v = rmax[mt][hh];
            v = fmaxf(v, __shfl_xor_sync(0xffffffffu, v, 1));
            v = fmaxf(v, __shfl_xor_sync(0xffffffffu, v, 2));
            rmax[mt][hh] = v;
        }
    float* smax = (float*)sm;            // [2][128]
    float* sinv = (float*)sm + 256;      // [128]
    if (t == 0) {
        const int wh = wid >> 2;
        #pragma unroll
        for (int mt = 0; mt < 2; ++mt) {
            smax[wh * 128 + wm + mt * 16 + g]     = rmax[mt][0];
            smax[wh * 128 + wm + mt * 16 + g + 8] = rmax[mt][1];
        }
    }
    __syncthreads();
    if (tid < 128) {
        const float m = fmaxf(smax[tid], smax[128 + tid]);
        sinv[tid] = (m > 0.f) ? (32767.0f / m) : 0.f;
        const int r = row0 + tid;
        if (r < M)
            d_S[blockIdx.y * NMAX + r] = m * (1.0f / 32767.0f);
    }
    __syncthreads();

    const int half_off = blockIdx.y * 256;
    #pragma unroll
    for (int mt = 0; mt < 2; ++mt) {
        const int rr0 = wm + mt * 16 + g;
        const int rr1 = rr0 + 8;
        const float i0 = sinv[rr0];
        const float i1 = sinv[rr1];
        const int r_lo = row0 + rr0, r_hi = row0 + rr1;
        #pragma unroll
        for (int nt = 0; nt < 8; ++nt) {
            const int colh = wn + nt * 8 + 2 * t;
            if (r_lo < M) {
                int v0 = __float2int_rn(c[mt][nt][0] * i0);
                int v1 = __float2int_rn(c[mt][nt][1] * i0);
                v0 = max(min(v0, 32767), -32767);
                v1 = max(min(v1, 32767), -32767);
                char* bp = d_QK8 + (size_t)r_lo * 512 + half_off;
                *(char2*)(bp + colh) = make_char2((char)(v0 >> 8), (char)(v1 >> 8));
                *(uchar2*)(bp + 128 + colh) =
                    make_uchar2((unsigned char)(v0 & 255), (unsigned char)(v1 & 255));
            }
            if (r_hi < M) {
                int v0 = __float2int_rn(c[mt][nt][2] * i1);
                int v1 = __float2int_rn(c[mt][nt][3] * i1);
                v0 = max(min(v0, 32767), -32767);
                v1 = max(min(v1, 32767), -32767);
                char* bp = d_QK8 + (size_t)r_hi * 512 + half_off;
                *(char2*)(bp + colh) = make_char2((char)(v0 >> 8), (char)(v1 >> 8));
                *(uchar2*)(bp + 128 + colh) =
                    make_uchar2((unsigned char)(v0 & 255), (unsigned char)(v1 & 255));
            }
        }
    }
}

// ---------------------------------------------------------------------------
// Per-edge gather + dot via dp4a on split-byte int16. 8 lanes/group,
// TWO consecutive edges per group (MLP 8) to close the latency/tail gap to
// the L2-BW roofline. dot = 65536*hh + 256*(hl+lh) + ll (exact int16 dot).
// ---------------------------------------------------------------------------
__device__ __forceinline__ float edge_dot(const char* qb, const char* kb, int sub)
{
    const int4 qh = *(const int4*)(qb + sub * 16);
    const int4 ql = *(const int4*)(qb + 128 + sub * 16);
    const int4 kh = *(const int4*)(kb + sub * 16);
    const int4 kl = *(const int4*)(kb + 128 + sub * 16);

    int hh = 0, hl = 0, lh = 0, ll = 0;
    const int* qhp = (const int*)&qh; const int* qlp = (const int*)&ql;
    const int* khp = (const int*)&kh; const int* klp = (const int*)&kl;
    #pragma unroll
    for (int j = 0; j < 4; ++j) {
        hh = dp4a_ss(qhp[j], khp[j], hh);
        hl = dp4a_su(qhp[j], klp[j], hl);
        lh = dp4a_us(qlp[j], khp[j], lh);
        ll = dp4a_uu(qlp[j], klp[j], ll);
    }
    return 65536.0f * (float)hh + 256.0f * (float)(hl + lh) + (float)ll;
}

__global__ __launch_bounds__(256) void edge_attn_q8(
    const int* __restrict__ ei, float* __restrict__ out, int E, int M)
{
    const int grp = (blockIdx.x * blockDim.x + threadIdx.x) >> 3;
    const int sub = threadIdx.x & 7;
    const int e0  = grp * 2;
    if (e0 >= E) return;
    const bool has1 = (e0 + 1 < E);

    int s0 = ei[e0];
    int d0 = ei[E + e0];
    s0 = min(max(s0, 0), M - 1);
    d0 = min(max(d0, 0), M - 1);
    int s1 = has1 ? ei[e0 + 1] : s0;
    int d1 = has1 ? ei[E + e0 + 1] : d0;
    s1 = min(max(s1, 0), M - 1);
    d1 = min(max(d1, 0), M - 1);

    float acc0 = edge_dot(d_QK8 + (size_t)s0 * 512,
                          d_QK8 + (size_t)d0 * 512 + 256, sub);
    float acc1 = edge_dot(d_QK8 + (size_t)s1 * 512,
                          d_QK8 + (size_t)d1 * 512 + 256, sub);

    acc0 += __shfl_xor_sync(0xffffffffu, acc0, 1);
    acc1 += __shfl_xor_sync(0xffffffffu, acc1, 1);
    acc0 += __shfl_xor_sync(0xffffffffu, acc0, 2);
    acc1 += __shfl_xor_sync(0xffffffffu, acc1, 2);
    acc0 += __shfl_xor_sync(0xffffffffu, acc0, 4);
    acc1 += __shfl_xor_sync(0xffffffffu, acc1, 4);

    if (sub == 0) {
        out[e0] = acc0 * d_S[s0] * d_S[NMAX + d0] * 0.08838834764831845f;
        if (has1)
            out[e0 + 1] = acc1 * d_S[s1] * d_S[NMAX + d1] * 0.08838834764831845f;
    }
}

// ---------------------------------------------------------------------------
extern "C" void kernel_launch(void* const* d_in, const int* in_sizes, int n_in,
                              void* d_out, int out_size)
{
    const float *X = nullptr, *Wq = nullptr, *Bq = nullptr, *Wk = nullptr, *Bk = nullptr;
    const int   *ei = nullptr;
    int ei_elems = 0, x_elems = 0;

    for (int i = 0; i < n_in; ++i) {
        const int sz = in_sizes[i];
        if (sz == W_DIM * IN_DIM) {
            if (!Wq) Wq = (const float*)d_in[i];
            else     Wk = (const float*)d_in[i];
        } else if (sz == W_DIM) {
            if (!Bq) Bq = (const float*)d_in[i];
            else     Bk = (const float*)d_in[i];
        } else if (sz > 4000000) {
            X = (const float*)d_in[i];
            x_elems = sz;
        } else {
            ei = (const int*)d_in[i];
            ei_elems = sz;
        }
    }

    const int M = x_elems / IN_DIM;    // 50000
    const int E = ei_elems / 2;        // 1600000
    const int x_f4 = x_elems / 4;
    float* out = (float*)d_out;

    static int smem_set = 0;
    if (!smem_set) {
        cudaFuncSetAttribute(gemm_qk_mma,
                             cudaFuncAttributeMaxDynamicSharedMemorySize, SMEM_TOTAL);
        smem_set = 1;
    }

    const int prep_total = W_F4 + x_f4;
    prep_all<<<(prep_total + 255) / 256, 256>>>(Wq, Wk, X, x_f4);

    dim3 grid_g((M + BM - 1) / BM, 2);
    gemm_qk_mma<<<grid_g, 256, SMEM_TOTAL>>>(Bq, Bk, M);

    const int ngroups = (E + 1) / 2;
    const int threads = 256;
    const int blocks  = (ngroups * 8 + threads - 1) / threads;
    edge_attn_q8<<<blocks, threads>>>(ei, out, E, M);
}

// round 17
// speedup vs baseline: 2.0230x; 1.0543x over previous
#include <cuda_runtime.h>
#include <cuda_fp16.h>
#include <cstdint>

#define NMAX    50000
#define IN_DIM  256
#define W_DIM   128
#define BM      128           // M rows per CTA
#define BN      128           // N cols per CTA (blockIdx.y -> Wq/Wk)
#define KC      64            // K chunk
#define NCH     (IN_DIM / KC) // 4 chunks
#define AP      72            // padded row stride (halves): conflict-free LDS

// Quantized QK, int16 split into bytes. Per node row (512B):
//   [0,128) q hi (s8)  [128,256) q lo (u8)  [256,384) k hi (s8)  [384,512) k lo (u8)
__device__ char d_QK8[(size_t)NMAX * 512];
// Per-row-half scales: [0,NMAX) = q, [NMAX,2*NMAX) = k. value = int * scale.
__device__ float d_S[2 * NMAX];
// fp16 weights: rows 0-127 = Wq, 128-255 = Wk
__device__ half d_Wh[256 * IN_DIM];

// smem: [buf][2 tiles][BM*AP halves]; tiles: 0=A 1=B
#define TILE_H   (BM * AP)                    // 9216 halves
#define BUF_H    (2 * TILE_H)                 // 18432 halves
#define SMEM_TOTAL (2 * BUF_H * 2)            // 73728 B

// m16n8k16 f16 MMA, fp32 accumulate
#define MMA16816(c, a, b)                                                     \
    asm volatile(                                                             \
        "mma.sync.aligned.m16n8k16.row.col.f32.f16.f16.f32 "                  \
        "{%0,%1,%2,%3}, {%4,%5,%6,%7}, {%8,%9}, {%0,%1,%2,%3};"               \
        : "+f"((c)[0]), "+f"((c)[1]), "+f"((c)[2]), "+f"((c)[3])              \
        : "r"((a)[0]), "r"((a)[1]), "r"((a)[2]), "r"((a)[3]),                 \
          "r"((b)[0]), "r"((b)[1]))

// cp.async 16B gmem->smem
#define CP_ASYNC16(smem_u32_, gptr)                                           \
    asm volatile("cp.async.ca.shared.global [%0], [%1], 16;"                  \
                 :: "r"(smem_u32_), "l"(gptr) : "memory")
#define CP_COMMIT()  asm volatile("cp.async.commit_group;" ::: "memory")
#define CP_WAIT(n)   asm volatile("cp.async.wait_group %0;" :: "n"(n) : "memory")

__device__ __forceinline__ uint32_t smem_u32(const void* p) {
    uint32_t a;
    asm("{ .reg .u64 t; cvta.to.shared.u64 t, %1; cvt.u32.u64 %0, t; }" : "=r"(a) : "l"(p));
    return a;
}

// dp4a variants
__device__ __forceinline__ int dp4a_ss(int a, int b, int c) {
    int d; asm("dp4a.s32.s32 %0,%1,%2,%3;" : "=r"(d) : "r"(a), "r"(b), "r"(c)); return d;
}
__device__ __forceinline__ int dp4a_su(int a, int b, int c) {
    int d; asm("dp4a.s32.u32 %0,%1,%2,%3;" : "=r"(d) : "r"(a), "r"(b), "r"(c)); return d;
}
__device__ __forceinline__ int dp4a_us(int a, int b, int c) {
    int d; asm("dp4a.u32.s32 %0,%1,%2,%3;" : "=r"(d) : "r"(a), "r"(b), "r"(c)); return d;
}
__device__ __forceinline__ int dp4a_uu(int a, int b, int c) {
    int d; asm("dp4a.u32.u32 %0,%1,%2,%3;" : "=r"(d) : "r"(a), "r"(b), "r"(c)); return d;
}

// ---------------------------------------------------------------------------
// One-time fp16 pack of W only ([Wq;Wk] -> d_Wh). 64 blocks.
// ---------------------------------------------------------------------------
#define W_F4 (256 * IN_DIM / 4)   // 16384
__global__ __launch_bounds__(256) void prep_w(
    const float* __restrict__ Wq, const float* __restrict__ Wk)
{
    const int i = blockIdx.x * 256 + threadIdx.x;
    const int base = i * 4;
    const int n = base >> 8, col = base & 255;
    const float4 v = (n < W_DIM)
        ? *(const float4*)(Wq + n * IN_DIM + col)
        : *(const float4*)(Wk + (n - W_DIM) * IN_DIM + col);
    *(half2*)(d_Wh + base)     = __floats2half2_rn(v.x, v.y);
    *(half2*)(d_Wh + base + 2) = __floats2half2_rn(v.z, v.w);
}

// ---------------------------------------------------------------------------
// Tensor-core projection + fused int16 quantization (stored as s8hi/u8lo).
// fp16 GEMM; A converted from fp32 X in-kernel (transient regs, placed after
// MMA so 2 CTAs/SM hold); B via cp.async from prepacked d_Wh.
// ---------------------------------------------------------------------------
__global__ void __launch_bounds__(256, 2) gemm_qk_mma(
    const float* __restrict__ X,
    const float* __restrict__ Bq, const float* __restrict__ Bk, int M)
{
    extern __shared__ half sm[];
    const float* __restrict__ Bv = blockIdx.y ? Bk : Bq;

    const int tid  = threadIdx.x;
    const int wid  = tid >> 5;
    const int lane = tid & 31;
    const int g    = lane >> 2;
    const int t    = lane & 3;
    const int wm   = (wid & 3) * 32;
    const int wn   = (wid >> 2) * 64;
    const int row0 = blockIdx.x * BM;
    const int nbase = blockIdx.y * BN;

    const int s_row = tid >> 3;          // B staging: 0..31
    const int s_seg = (tid & 7) * 16;

    float c[2][8][4];
    #pragma unroll
    for (int mt = 0; mt < 2; ++mt)
        #pragma unroll
        for (int nt = 0; nt < 8; ++nt)
            #pragma unroll
            for (int i = 0; i < 4; ++i) c[mt][nt][i] = 0.f;

    // B: cp.async fp16 tile for chunk ch into buffer bsel
    auto issue_B = [&](int ch, int bsel) {
        half* Bs = sm + bsel * BUF_H + TILE_H;
        const uint32_t bs_u32 = smem_u32(Bs);
        #pragma unroll
        for (int i = 0; i < 4; ++i) {
            const int row = s_row + i * 32;
            const char* bsrc = (const char*)(d_Wh + (size_t)(nbase + row) * IN_DIM + ch * KC) + s_seg;
            CP_ASYNC16(bs_u32 + row * (AP * 2) + s_seg, bsrc);
        }
        CP_COMMIT();
    };

    // A: load fp32 X chunk, convert to fp16, store to tile (transient regs)
    auto stage_A = [&](int ch, int bsel) {
        half* As = sm + bsel * BUF_H;
        #pragma unroll
        for (int i = 0; i < 8; ++i) {
            const int p  = tid + i * 256;
            const int r  = p >> 4;
            const int c4 = (p & 15) * 4;
            const int gr = min(row0 + r, M - 1);
            const float4 x = *(const float4*)(X + (size_t)gr * IN_DIM + ch * KC + c4);
            const int off = r * AP + c4;
            *(half2*)(As + off)     = __floats2half2_rn(x.x, x.y);
            *(half2*)(As + off + 2) = __floats2half2_rn(x.z, x.w);
        }
    };

    // prologue: chunk 0 into buf 0
    issue_B(0, 0);
    stage_A(0, 0);

    for (int ch = 0; ch < NCH; ++ch) {
        if (ch + 1 < NCH) { issue_B(ch + 1, (ch + 1) & 1); CP_WAIT(1); }
        else              { CP_WAIT(0); }
        __syncthreads();   // A stores + B cp.async for chunk ch visible

        {
            half* As = sm + (ch & 1) * BUF_H;
            half* Bs = As + TILE_H;

            #pragma unroll
            for (int ks = 0; ks < KC / 16; ++ks) {
                const int kb = ks * 16 + 2 * t;

                uint32_t ah[2][4];
                #pragma unroll
                for (int mt = 0; mt < 2; ++mt) {
                    const int rb = wm + mt * 16 + g;
                    ah[mt][0] = *(const uint32_t*)(As + (rb    ) * AP + kb);
                    ah[mt][1] = *(const uint32_t*)(As + (rb + 8) * AP + kb);
                    ah[mt][2] = *(const uint32_t*)(As + (rb    ) * AP + kb + 8);
                    ah[mt][3] = *(const uint32_t*)(As + (rb + 8) * AP + kb + 8);
                }
                #pragma unroll
                for (int nt = 0; nt < 8; ++nt) {
                    const int nb = wn + nt * 8 + g;
                    uint32_t bh[2];
                    bh[0] = *(const uint32_t*)(Bs + nb * AP + kb);
                    bh[1] = *(const uint32_t*)(Bs + nb * AP + kb + 8);
                    #pragma unroll
                    for (int mt = 0; mt < 2; ++mt)
                        MMA16816(c[mt][nt], ah[mt], bh);
                }
            }
        }

        if (ch + 1 < NCH)
            stage_A(ch + 1, (ch + 1) & 1);   // disjoint from buf ch being read
        __syncthreads();   // MMA(ch) done + A(ch+1) stores done before refill
    }

    // ====== epilogue: bias + row absmax + int16 quantize -> s8hi/u8lo ======
    float rmax[2][2];
    #pragma unroll
    for (int mt = 0; mt < 2; ++mt) { rmax[mt][0] = 0.f; rmax[mt][1] = 0.f; }
    #pragma unroll
    for (int mt = 0; mt < 2; ++mt)
        #pragma unroll
        for (int nt = 0; nt < 8; ++nt) {
            const float2 b = *(const float2*)(Bv + wn + nt * 8 + 2 * t);
            c[mt][nt][0] += b.x; c[mt][nt][1] += b.y;
            c[mt][nt][2] += b.x; c[mt][nt][3] += b.y;
            rmax[mt][0] = fmaxf(rmax[mt][0],
                                fmaxf(fabsf(c[mt][nt][0]), fabsf(c[mt][nt][1])));
            rmax[mt][1] = fmaxf(rmax[mt][1],
                                fmaxf(fabsf(c[mt][nt][2]), fabsf(c[mt][nt][3])));
        }
    #pragma unroll
    for (int mt = 0; mt < 2; ++mt)
        #pragma unroll
        for (int hh = 0; hh < 2; ++hh) {
            float v = rmax[mt][hh];
            v = fmaxf(v, __shfl_xor_sync(0xffffffffu, v, 1));
            v = fmaxf(v, __shfl_xor_sync(0xffffffffu, v, 2));
            rmax[mt][hh] = v;
        }
    float* smax = (float*)sm;            // [2][128]
    float* sinv = (float*)sm + 256;      // [128]
    if (t == 0) {
        const int wh = wid >> 2;
        #pragma unroll
        for (int mt = 0; mt < 2; ++mt) {
            smax[wh * 128 + wm + mt * 16 + g]     = rmax[mt][0];
            smax[wh * 128 + wm + mt * 16 + g + 8] = rmax[mt][1];
        }
    }
    __syncthreads();
    if (tid < 128) {
        const float m = fmaxf(smax[tid], smax[128 + tid]);
        sinv[tid] = (m > 0.f) ? (32767.0f / m) : 0.f;
        const int r = row0 + tid;
        if (r < M)
            d_S[blockIdx.y * NMAX + r] = m * (1.0f / 32767.0f);
    }
    __syncthreads();

    const int half_off = blockIdx.y * 256;
    #pragma unroll
    for (int mt = 0; mt < 2; ++mt) {
        const int rr0 = wm + mt * 16 + g;
        const int rr1 = rr0 + 8;
        const float i0 = sinv[rr0];
        const float i1 = sinv[rr1];
        const int r_lo = row0 + rr0, r_hi = row0 + rr1;
        #pragma unroll
        for (int nt = 0; nt < 8; ++nt) {
            const int colh = wn + nt * 8 + 2 * t;
            if (r_lo < M) {
                int v0 = __float2int_rn(c[mt][nt][0] * i0);
                int v1 = __float2int_rn(c[mt][nt][1] * i0);
                v0 = max(min(v0, 32767), -32767);
                v1 = max(min(v1, 32767), -32767);
                char* bp = d_QK8 + (size_t)r_lo * 512 + half_off;
                *(char2*)(bp + colh) = make_char2((char)(v0 >> 8), (char)(v1 >> 8));
                *(uchar2*)(bp + 128 + colh) =
                    make_uchar2((unsigned char)(v0 & 255), (unsigned char)(v1 & 255));
            }
            if (r_hi < M) {
                int v0 = __float2int_rn(c[mt][nt][2] * i1);
                int v1 = __float2int_rn(c[mt][nt][3] * i1);
                v0 = max(min(v0, 32767), -32767);
                v1 = max(min(v1, 32767), -32767);
                char* bp = d_QK8 + (size_t)r_hi * 512 + half_off;
                *(char2*)(bp + colh) = make_char2((char)(v0 >> 8), (char)(v1 >> 8));
                *(uchar2*)(bp + 128 + colh) =
                    make_uchar2((unsigned char)(v0 & 255), (unsigned char)(v1 & 255));
            }
        }
    }
}

// ---------------------------------------------------------------------------
// Per-edge gather + dot via dp4a on split-byte int16. 8 lanes/group,
// two consecutive edges per group (MLP 8). Exact int16 dot:
//   dot = 65536*hh + 256*(hl+lh) + ll
// ---------------------------------------------------------------------------
__device__ __forceinline__ float edge_dot(const char* qb, const char* kb, int sub)
{
    const int4 qh = *(const int4*)(qb + sub * 16);
    const int4 ql = *(const int4*)(qb + 128 + sub * 16);
    const int4 kh = *(const int4*)(kb + sub * 16);
    const int4 kl = *(const int4*)(kb + 128 + sub * 16);

    int hh = 0, hl = 0, lh = 0, ll = 0;
    const int* qhp = (const int*)&qh; const int* qlp = (const int*)&ql;
    const int* khp = (const int*)&kh; const int* klp = (const int*)&kl;
    #pragma unroll
    for (int j = 0; j < 4; ++j) {
        hh = dp4a_ss(qhp[j], khp[j], hh);
        hl = dp4a_su(qhp[j], klp[j], hl);
        lh = dp4a_us(qlp[j], khp[j], lh);
        ll = dp4a_uu(qlp[j], klp[j], ll);
    }
    return 65536.0f * (float)hh + 256.0f * (float)(hl + lh) + (float)ll;
}

__global__ __launch_bounds__(256) void edge_attn_q8(
    const int* __restrict__ ei, float* __restrict__ out, int E, int M)
{
    const int grp = (blockIdx.x * blockDim.x + threadIdx.x) >> 3;
    const int sub = threadIdx.x & 7;
    const int e0  = grp * 2;
    if (e0 >= E) return;
    const bool has1 = (e0 + 1 < E);

    int s0 = ei[e0];
    int d0 = ei[E + e0];
    s0 = min(max(s0, 0), M - 1);
    d0 = min(max(d0, 0), M - 1);
    int s1 = has1 ? ei[e0 + 1] : s0;
    int d1 = has1 ? ei[E + e0 + 1] : d0;
    s1 = min(max(s1, 0), M - 1);
    d1 = min(max(d1, 0), M - 1);

    float acc0 = edge_dot(d_QK8 + (size_t)s0 * 512,
                          d_QK8 + (size_t)d0 * 512 + 256, sub);
    float acc1 = edge_dot(d_QK8 + (size_t)s1 * 512,
                          d_QK8 + (size_t)d1 * 512 + 256, sub);

    acc0 += __shfl_xor_sync(0xffffffffu, acc0, 1);
    acc1 += __shfl_xor_sync(0xffffffffu, acc1, 1);
    acc0 += __shfl_xor_sync(0xffffffffu, acc0, 2);
    acc1 += __shfl_xor_sync(0xffffffffu, acc1, 2);
    acc0 += __shfl_xor_sync(0xffffffffu, acc0, 4);
    acc1 += __shfl_xor_sync(0xffffffffu, acc1, 4);

    if (sub == 0) {
        out[e0] = acc0 * d_S[s0] * d_S[NMAX + d0] * 0.08838834764831845f;
        if (has1)
            out[e0 + 1] = acc1 * d_S[s1] * d_S[NMAX + d1] * 0.08838834764831845f;
    }
}

// ---------------------------------------------------------------------------
extern "C" void kernel_launch(void* const* d_in, const int* in_sizes, int n_in,
                              void* d_out, int out_size)
{
    const float *X = nullptr, *Wq = nullptr, *Bq = nullptr, *Wk = nullptr, *Bk = nullptr;
    const int   *ei = nullptr;
    int ei_elems = 0, x_elems = 0;

    for (int i = 0; i < n_in; ++i) {
        const int sz = in_sizes[i];
        if (sz == W_DIM * IN_DIM) {
            if (!Wq) Wq = (const float*)d_in[i];
            else     Wk = (const float*)d_in[i];
        } else if (sz == W_DIM) {
            if (!Bq) Bq = (const float*)d_in[i];
            else     Bk = (const float*)d_in[i];
        } else if (sz > 4000000) {
            X = (const float*)d_in[i];
            x_elems = sz;
        } else {
            ei = (const int*)d_in[i];
            ei_elems = sz;
        }
    }

    const int M = x_elems / IN_DIM;    // 50000
    const int E = ei_elems / 2;        // 1600000
    float* out = (float*)d_out;

    static int smem_set = 0;
    if (!smem_set) {
        cudaFuncSetAttribute(gemm_qk_mma,
                             cudaFuncAttributeMaxDynamicSharedMemorySize, SMEM_TOTAL);
        smem_set = 1;
    }

    prep_w<<<W_F4 / 256, 256>>>(Wq, Wk);

    dim3 grid_g((M + BM - 1) / BM, 2);
    gemm_qk_mma<<<grid_g, 256, SMEM_TOTAL>>>(X, Bq, Bk, M);

    const int ngroups = (E + 1) / 2;
    const int threads = 256;
    const int blocks  = (ngroups * 8 + threads - 1) / threads;
    edge_attn_q8<<<blocks, threads>>>(ei, out, E, M);
}